// round 12
// baseline (speedup 1.0000x reference)
#include <cuda_runtime.h>
#include <math.h>
#include <stdint.h>

#define BB   32
#define SS   256
#define NN   50
#define DD   100
#define QDIM 768

#define NT   13      // n-tiles over 104 cols = 100 v-rows (2 s) + 4 pad
#define KT   13      // k-tiles over 104 (100 used)
#define AP   108     // v-tile row stride (floats), conflict-free
#define PAIRS_PER_BLK 2
#define THREADS 192
#define AF_PER_B (7 * KT * 128)   // floats per batch in g_Af = 11648

__device__ float g_Qraw[BB * DD];
__device__ float g_cb[BB];
__device__ float g_Af[BB * AF_PER_B];   // A-frags of [W; w~] : [b][tile][kt][lane][4]
__device__ float g_T[BB * SS * DD];     // t = att @ v (exact fp32)
__device__ float g_sig[BB * SS];        // sum of final att per row

// ---------------------------------------------------------------------------
__device__ __forceinline__ void mma_tf32(float c[4], const float* a,
                                         float b0, float b1)
{
    asm volatile(
        "mma.sync.aligned.m16n8k8.row.col.f32.tf32.tf32.f32 "
        "{%0,%1,%2,%3}, {%4,%5,%6,%7}, {%8,%9}, {%0,%1,%2,%3};\n"
        : "+f"(c[0]), "+f"(c[1]), "+f"(c[2]), "+f"(c[3])
        : "r"(__float_as_uint(a[0])), "r"(__float_as_uint(a[1])),
          "r"(__float_as_uint(a[2])), "r"(__float_as_uint(a[3])),
          "r"(__float_as_uint(b0)),  "r"(__float_as_uint(b1)));
}

// ---------------------------------------------------------------------------
// Kernel 1a: g_Qraw[b][e] = q[b] . Qw[e] + Qb[e]
// ---------------------------------------------------------------------------
__global__ __launch_bounds__(128) void qproj_a(
    const float* __restrict__ q,
    const float* __restrict__ Qw,
    const float* __restrict__ Qb)
{
    int b = blockIdx.x / DD, e = blockIdx.x % DD;
    __shared__ float red[4];
    const float* qr = q + (size_t)b * QDIM;
    const float* wr = Qw + (size_t)e * QDIM;
    int tid = threadIdx.x, warp = tid >> 5, lane = tid & 31;

    float acc = 0.f;
    #pragma unroll 6
    for (int i = tid; i < QDIM; i += 128) acc += qr[i] * wr[i];
    #pragma unroll
    for (int o = 16; o; o >>= 1) acc += __shfl_xor_sync(0xffffffffu, acc, o);
    if (lane == 0) red[warp] = acc;
    __syncthreads();
    if (tid == 0)
        g_Qraw[b * DD + e] = red[0] + red[1] + red[2] + red[3] + Qb[e];
}

// ---------------------------------------------------------------------------
// Kernel 1b: per batch: normalize Q, w~ = Vw^T Qn, cb = Qn.Vb, build A frags
// A GEMM rows: 0..99 = W rows, 100 = w~, 101..111 = 0; cols >= 100 -> 0
// ---------------------------------------------------------------------------
__global__ __launch_bounds__(128) void qproj_b(
    const float* __restrict__ Vw,
    const float* __restrict__ Vb)
{
    int b = blockIdx.x;
    __shared__ float sQ[DD];
    __shared__ float sWq[DD];
    __shared__ float red[4];

    int tid = threadIdx.x, warp = tid >> 5, lane = tid & 31;

    float qv = (tid < DD) ? g_Qraw[b * DD + tid] : 0.f;
    float ss = qv * qv;
    #pragma unroll
    for (int o = 16; o; o >>= 1) ss += __shfl_xor_sync(0xffffffffu, ss, o);
    if (lane == 0) red[warp] = ss;
    __syncthreads();
    if (tid == 0)
        red[0] = fmaxf(sqrtf(red[0] + red[1] + red[2] + red[3]), 1e-12f);
    __syncthreads();
    float inv = 1.0f / red[0];
    if (tid < DD) sQ[tid] = qv * inv;
    __syncthreads();

    if (tid < DD) {
        float a = 0.f;
        #pragma unroll 4
        for (int e = 0; e < DD; e++) a += sQ[e] * Vw[e * DD + tid];
        sWq[tid] = a;
    }
    if (warp == 0) {
        float a = 0.f;
        for (int e = lane; e < DD; e += 32) a += sQ[e] * Vb[e];
        #pragma unroll
        for (int o = 16; o; o >>= 1) a += __shfl_xor_sync(0xffffffffu, a, o);
        if (lane == 0) g_cb[b] = a;
    }
    __syncthreads();

    float* dst = g_Af + (size_t)b * AF_PER_B;
    for (int i = tid; i < 7 * KT * 32; i += 128) {
        int ln = i & 31;
        int kt = (i >> 5) % KT;
        int w  = (i >> 5) / KT;
        int g = ln >> 2, tg = ln & 3;
        int m0 = w * 16 + g, m1 = m0 + 8;
        int k0 = kt * 8 + tg, k1 = k0 + 4;
        float a0 = 0.f, a1 = 0.f, a2 = 0.f, a3 = 0.f;
        if (m0 < 100) {
            if (k0 < 100) a0 = Vw[m0 * DD + k0];
            if (k1 < 100) a2 = Vw[m0 * DD + k1];
        } else if (m0 == 100) {
            if (k0 < 100) a0 = sWq[k0];
            if (k1 < 100) a2 = sWq[k1];
        }
        if (m1 < 100) {
            if (k0 < 100) a1 = Vw[m1 * DD + k0];
            if (k1 < 100) a3 = Vw[m1 * DD + k1];
        } else if (m1 == 100) {
            if (k0 < 100) a1 = sWq[k0];
            if (k1 < 100) a3 = sWq[k1];
        }
        float4 val = make_float4(a0, a1, a2, a3);
        *(float4*)(dst + (size_t)(w * KT + kt) * 128 + ln * 4) = val;
    }
}

// ---------------------------------------------------------------------------
// Kernel 2: 4 GEMM warps x 2 m-tiles (tiles w and w+4). Each B fragment read
// feeds 2 mma -> smem crossbar traffic ~halved vs 7-warp version.
// ---------------------------------------------------------------------------
#define F_V     0
#define F_PART  (F_V + 104 * AP)            // 8 * 112 (tile 7 = dump row)
#define F_DOT   (F_PART + 8 * 112)          // 112
#define F_ATT   (F_DOT + 112)               // 128
#define SMEM_FLOATS_TOT (F_ATT + 128)

__global__ __launch_bounds__(THREADS, 2) void attn_kernel(
    const float* __restrict__ v,
    const float* __restrict__ Vb)
{
    extern __shared__ float smf[];
    float* sV    = smf + F_V;
    float* sPart = smf + F_PART;
    float* sdot  = smf + F_DOT;
    float* sAtt  = smf + F_ATT;

    int tid  = threadIdx.x;
    int warp = tid >> 5;
    int lane = tid & 31;
    int g    = lane >> 2;
    int tg   = lane & 3;

    int blk   = blockIdx.x;                  // 2048 blocks
    int b     = blk >> 6;
    int pair0 = (blk & 63) * PAIRS_PER_BLK;

    float cb = g_cb[b];

    // A fragments for 2 m-tiles: tileA = warp, tileB = warp + 4 (<7)
    float4 aW0[KT], aW1[KT];
    float biasA0 = 0.f, biasA1 = 0.f, biasB0 = 0.f, biasB1 = 0.f;
    float mvalB0 = 0.f, mvalB1 = 0.f;
    if (warp < 4) {
        const float4* srcA = (const float4*)(g_Af + (size_t)b * AF_PER_B
                                             + (size_t)warp * KT * 128);
        #pragma unroll
        for (int kt = 0; kt < KT; kt++) aW0[kt] = srcA[kt * 32 + lane];
        if (warp < 3) {
            const float4* srcB = (const float4*)(g_Af + (size_t)b * AF_PER_B
                                                 + (size_t)(warp + 4) * KT * 128);
            #pragma unroll
            for (int kt = 0; kt < KT; kt++) aW1[kt] = srcB[kt * 32 + lane];
        } else {
            #pragma unroll
            for (int kt = 0; kt < KT; kt++)
                aW1[kt] = make_float4(0.f, 0.f, 0.f, 0.f);
        }
        int mA0 = warp * 16 + g;           // < 64, always valid
        biasA0 = Vb[mA0];
        biasA1 = Vb[mA0 + 8];
        int mB0 = warp * 16 + 64 + g;
        if (mB0 < 100)     { biasB0 = Vb[mB0];     mvalB0 = 1.f; }
        if (mB0 + 8 < 100) { biasB1 = Vb[mB0 + 8]; mvalB1 = 1.f; }
    }

    // one-time pad zeroing of the v tile
    if (tid < 200) {
        int r = tid >> 1, h = tid & 1;
        *(float4*)(sV + r * AP + 100 + 4 * h) = make_float4(0.f, 0.f, 0.f, 0.f);
    }
    for (int i = tid; i < 4 * AP; i += THREADS) sV[100 * AP + i] = 0.f;

    for (int p = 0; p < PAIRS_PER_BLK; p++) {
        __syncthreads();

        int pp = b * 128 + pair0 + p;
        size_t vbase = (size_t)pp * 10000;
        for (int c = tid; c < 2500; c += THREADS) {
            int r = c / 25, dq = (c - r * 25) * 4;
            float4 val = *(const float4*)(v + vbase + r * DD + dq);
            *(float4*)(sV + r * AP + dq) = val;
        }
        __syncthreads();

        // ---- GEMM: warps 0..3; each B-read feeds 2 mma ----
        if (warp < 4) {
            #pragma unroll 1
            for (int nt = 0; nt < NT; nt++) {
                const float* br = sV + (nt * 8 + g) * AP + tg;
                float c0[4] = {0.f, 0.f, 0.f, 0.f};
                float c1[4] = {0.f, 0.f, 0.f, 0.f};
                #pragma unroll
                for (int kt = 0; kt < KT; kt++) {
                    float b0 = br[kt * 8], b1 = br[kt * 8 + 4];
                    mma_tf32(c0, (const float*)&aW0[kt], b0, b1);
                    mma_tf32(c1, (const float*)&aW1[kt], b0, b1);
                }
                // squares per column; tileA rows always valid
                float k0 = c0[0] + biasA0, k1 = c0[1] + biasA0;
                float k2 = c0[2] + biasA1, k3 = c0[3] + biasA1;
                float sa0 = k0 * k0 + k2 * k2;
                float sa1 = k1 * k1 + k3 * k3;
                float m0v = c1[0] + biasB0, m1v = c1[1] + biasB0;
                float m2v = c1[2] + biasB1, m3v = c1[3] + biasB1;
                float sb0 = mvalB0 * m0v * m0v + mvalB1 * m2v * m2v;
                float sb1 = mvalB0 * m1v * m1v + mvalB1 * m3v * m3v;
                #pragma unroll
                for (int o = 4; o <= 16; o <<= 1) {
                    sa0 += __shfl_xor_sync(0xffffffffu, sa0, o);
                    sa1 += __shfl_xor_sync(0xffffffffu, sa1, o);
                    sb0 += __shfl_xor_sync(0xffffffffu, sb0, o);
                    sb1 += __shfl_xor_sync(0xffffffffu, sb1, o);
                }
                if (g == 0) {
                    int col = nt * 8 + 2 * tg;
                    sPart[warp * 112 + col]           = sa0;
                    sPart[warp * 112 + col + 1]       = sa1;
                    sPart[(warp + 4) * 112 + col]     = sb0;  // warp3 -> dump row 7
                    sPart[(warp + 4) * 112 + col + 1] = sb1;
                }
                if (warp == 2 && g == 4) {   // tileB row 100 = numerator
                    sdot[nt * 8 + 2 * tg]     = c1[0] + cb;
                    sdot[nt * 8 + 2 * tg + 1] = c1[1] + cb;
                }
            }
        }
        __syncthreads();

        // ---- softmax per s (warps 0,1); folds the 7-way partial sum ----
        if (warp < 2) {
            int s = warp;
            int rb = s * 50;
            float x0, x1;
            {
                int r = rb + lane;
                float nrm = 0.f;
                #pragma unroll
                for (int w = 0; w < 7; w++) nrm += sPart[w * 112 + r];
                float l2 = sqrtf(nrm);
                if (l2 == 0.0f) l2 = 1e-6f;
                float sc = sdot[r] / l2;
                sc = (sc == 0.0f) ? -10000.0f : sc;
                x0 = (sc > 0.0f) ? sc : 0.01f * sc;
            }
            x1 = -INFINITY;
            if (lane < NN - 32) {
                int r = rb + lane + 32;
                float nrm = 0.f;
                #pragma unroll
                for (int w = 0; w < 7; w++) nrm += sPart[w * 112 + r];
                float l2 = sqrtf(nrm);
                if (l2 == 0.0f) l2 = 1e-6f;
                float sc = sdot[r] / l2;
                sc = (sc == 0.0f) ? -10000.0f : sc;
                x1 = (sc > 0.0f) ? sc : 0.01f * sc;
            }
            float m = fmaxf(x0, x1);
            #pragma unroll
            for (int o = 16; o; o >>= 1) m = fmaxf(m, __shfl_xor_sync(0xffffffffu, m, o));
            float e0 = expf(x0 - m);
            float e1 = (lane < NN - 32) ? expf(x1 - m) : 0.0f;
            float sm = e0 + e1;
            #pragma unroll
            for (int o = 16; o; o >>= 1) sm += __shfl_xor_sync(0xffffffffu, sm, o);
            float inv = 1.0f / sm;
            float a0 = e0 * inv;
            if (a0 == (1.0f / 50.0f)) a0 = 0.0f;
            float a1 = 0.0f;
            if (lane < NN - 32) {
                a1 = e1 * inv;
                if (a1 == (1.0f / 50.0f)) a1 = 0.0f;
            }
            sAtt[rb + lane] = a0;
            if (lane < NN - 32) sAtt[rb + lane + 32] = a1;
            float sg = a0 + a1;
            #pragma unroll
            for (int o = 16; o; o >>= 1) sg += __shfl_xor_sync(0xffffffffu, sg, o);
            if (lane == 0) g_sig[pp * 2 + s] = sg;
        }
        __syncthreads();

        // ---- t[s][e] = sum_n att[s][n] * v[s*50+n][e]  (exact fp32) ----
        for (int i = tid; i < 200; i += THREADS) {
            int s = i / 100, e = i - 100 * s;
            float acc = 0.f;
            const float* ab = sAtt + s * 50;
            const float* kb = sV + (s * 50) * AP + e;
            #pragma unroll 5
            for (int n = 0; n < NN; n++) acc += ab[n] * kb[n * AP];
            g_T[(size_t)(pp * 2 + s) * DD + e] = acc;
        }
    }
}

// ---------------------------------------------------------------------------
// Kernel 3: out[r][e] = sum_d T[r][d] * W[e][d] + sig[r] * Vb[e]
// 512 threads, 32 rows/block; T read as broadcast float4 (crossbar-light).
// ---------------------------------------------------------------------------
#define OP_ROWS 32
#define WS 101
__global__ __launch_bounds__(512) void out_proj(
    const float* __restrict__ Vw,
    const float* __restrict__ Vb,
    float* __restrict__ out)
{
    __shared__ float sW[DD * WS];          // sW[d*101+e] = Vw[e*100+d]
    __shared__ float sT[OP_ROWS * DD];
    __shared__ float sS[OP_ROWS];

    int tid = threadIdx.x;
    int r0  = blockIdx.x * OP_ROWS;

    for (int i = tid; i < DD * DD; i += 512) {
        int e = i / DD, d = i - e * DD;     // coalesced LDG, conflict-free STS
        sW[d * WS + e] = Vw[i];
    }
    {
        const float4* tsrc = (const float4*)(g_T + (size_t)r0 * DD);
        float4* tdst = (float4*)sT;
        for (int i = tid; i < OP_ROWS * DD / 4; i += 512) tdst[i] = tsrc[i];
        if (tid < OP_ROWS) sS[tid] = g_sig[r0 + tid];
    }
    __syncthreads();

    int grp = tid >> 7;          // 0..3 -> rows grp*8 .. grp*8+7
    int e   = tid & 127;
    if (e < DD) {
        float be = Vb[e];
        float acc[8];
        #pragma unroll
        for (int j = 0; j < 8; j++) acc[j] = sS[grp * 8 + j] * be;
        #pragma unroll 1
        for (int dq = 0; dq < DD; dq += 4) {
            float4 t[8];
            #pragma unroll
            for (int j = 0; j < 8; j++)      // broadcast within warp
                t[j] = *(const float4*)&sT[(grp * 8 + j) * DD + dq];
            #pragma unroll
            for (int i = 0; i < 4; i++) {
                float w = sW[(dq + i) * WS + e];
                #pragma unroll
                for (int j = 0; j < 8; j++)
                    acc[j] += ((const float*)&t[j])[i] * w;
            }
        }
        #pragma unroll
        for (int j = 0; j < 8; j++)
            out[(size_t)(r0 + grp * 8 + j) * DD + e] = acc[j];
    }
}

// ---------------------------------------------------------------------------
extern "C" void kernel_launch(void* const* d_in, const int* in_sizes, int n_in,
                              void* d_out, int out_size)
{
    // metadata order: input_ent, q, k, v, Q_w, Q_b, V_w, V_b
    const float* q  = (const float*)d_in[1];
    const float* v  = (const float*)d_in[3];
    const float* Qw = (const float*)d_in[4];
    const float* Qb = (const float*)d_in[5];
    const float* Vw = (const float*)d_in[6];
    const float* Vb = (const float*)d_in[7];
    float* out = (float*)d_out;

    qproj_a<<<BB * DD, 128>>>(q, Qw, Qb);
    qproj_b<<<BB, 128>>>(Vw, Vb);

    size_t smem_bytes = SMEM_FLOATS_TOT * sizeof(float);
    cudaFuncSetAttribute(attn_kernel, cudaFuncAttributeMaxDynamicSharedMemorySize,
                         (int)smem_bytes);
    attn_kernel<<<BB * SS / 2 / PAIRS_PER_BLK, THREADS, smem_bytes>>>(v, Vb);

    out_proj<<<BB * SS / OP_ROWS, 512>>>(Vw, Vb, out);
}

// round 13
// speedup vs baseline: 1.8065x; 1.8065x over previous
#include <cuda_runtime.h>
#include <cuda_bf16.h>
#include <math.h>
#include <stdint.h>

#define BB   32
#define SS   256
#define NN   50
#define DD   100
#define QDIM 768

#define NT   13        // n-tiles over 104 cols = 100 v-rows (2 s) + 4 pad
#define KTB  7         // bf16 k-tiles (k16) over 112 (100 used)
#define VHW  68        // bf16 v-tile row stride in 32-bit words (136 bf16)
#define PAIRS_PER_BLK 2
#define AFB_PER_B (7 * KTB * 32 * 4)   // uints per batch = 6272

__device__ float    g_Qraw[BB * DD];
__device__ float    g_cb[BB];
__device__ uint32_t g_Af[BB * AFB_PER_B];  // bf16 A-frags of [W; w~]
__device__ float    g_T[BB * SS * DD];     // t = att @ v (exact fp32)
__device__ float    g_sig[BB * SS];

// ---------------------------------------------------------------------------
__device__ __forceinline__ void mma_bf16(float c[4], const uint32_t a[4],
                                         uint32_t b0, uint32_t b1)
{
    asm volatile(
        "mma.sync.aligned.m16n8k16.row.col.f32.bf16.bf16.f32 "
        "{%0,%1,%2,%3}, {%4,%5,%6,%7}, {%8,%9}, {%0,%1,%2,%3};\n"
        : "+f"(c[0]), "+f"(c[1]), "+f"(c[2]), "+f"(c[3])
        : "r"(a[0]), "r"(a[1]), "r"(a[2]), "r"(a[3]),
          "r"(b0), "r"(b1));
}

__device__ __forceinline__ uint32_t pack_bf16(float f0, float f1)
{
    uint16_t lo = __bfloat16_as_ushort(__float2bfloat16(f0));
    uint16_t hi = __bfloat16_as_ushort(__float2bfloat16(f1));
    return (uint32_t)lo | ((uint32_t)hi << 16);
}

// ---------------------------------------------------------------------------
// Kernel 1a: g_Qraw[b][e] = q[b] . Qw[e] + Qb[e]
// ---------------------------------------------------------------------------
__global__ __launch_bounds__(128) void qproj_a(
    const float* __restrict__ q,
    const float* __restrict__ Qw,
    const float* __restrict__ Qb)
{
    int b = blockIdx.x / DD, e = blockIdx.x % DD;
    __shared__ float red[4];
    const float* qr = q + (size_t)b * QDIM;
    const float* wr = Qw + (size_t)e * QDIM;
    int tid = threadIdx.x, warp = tid >> 5, lane = tid & 31;

    float acc = 0.f;
    #pragma unroll 6
    for (int i = tid; i < QDIM; i += 128) acc += qr[i] * wr[i];
    #pragma unroll
    for (int o = 16; o; o >>= 1) acc += __shfl_xor_sync(0xffffffffu, acc, o);
    if (lane == 0) red[warp] = acc;
    __syncthreads();
    if (tid == 0)
        g_Qraw[b * DD + e] = red[0] + red[1] + red[2] + red[3] + Qb[e];
}

// ---------------------------------------------------------------------------
// Kernel 1b: normalize Q, w~ = Vw^T Qn, cb = Qn.Vb, build bf16 A frags
// A rows: 0..99 = W rows, 100 = w~, 101..111 = 0; cols >= 100 -> 0
// ---------------------------------------------------------------------------
__global__ __launch_bounds__(128) void qproj_b(
    const float* __restrict__ Vw,
    const float* __restrict__ Vb)
{
    int b = blockIdx.x;
    __shared__ float sQ[DD];
    __shared__ float sWq[DD];
    __shared__ float red[4];

    int tid = threadIdx.x, warp = tid >> 5, lane = tid & 31;

    float qv = (tid < DD) ? g_Qraw[b * DD + tid] : 0.f;
    float ss = qv * qv;
    #pragma unroll
    for (int o = 16; o; o >>= 1) ss += __shfl_xor_sync(0xffffffffu, ss, o);
    if (lane == 0) red[warp] = ss;
    __syncthreads();
    if (tid == 0)
        red[0] = fmaxf(sqrtf(red[0] + red[1] + red[2] + red[3]), 1e-12f);
    __syncthreads();
    float inv = 1.0f / red[0];
    if (tid < DD) sQ[tid] = qv * inv;
    __syncthreads();

    if (tid < DD) {
        float a = 0.f;
        #pragma unroll 4
        for (int e = 0; e < DD; e++) a += sQ[e] * Vw[e * DD + tid];
        sWq[tid] = a;
    }
    if (warp == 0) {
        float a = 0.f;
        for (int e = lane; e < DD; e += 32) a += sQ[e] * Vb[e];
        #pragma unroll
        for (int o = 16; o; o >>= 1) a += __shfl_xor_sync(0xffffffffu, a, o);
        if (lane == 0) g_cb[b] = a;
    }
    __syncthreads();

    // build bf16 A fragments: layout [w][kt][lane][4regs], coalesced uint4
    uint32_t* dst = g_Af + (size_t)b * AFB_PER_B;
    for (int i = tid; i < 7 * KTB * 32; i += 128) {
        int ln = i & 31;
        int kt = (i >> 5) % KTB;
        int w  = (i >> 5) / KTB;
        int g = ln >> 2, tg = ln & 3;
        int m0 = w * 16 + g, m1 = m0 + 8;
        int k0 = kt * 16 + 2 * tg;

        float f[2][4];   // [row m0/m1][k0, k0+1, k0+8, k0+9]
        #pragma unroll
        for (int h = 0; h < 2; h++) {
            int m = h ? m1 : m0;
            #pragma unroll
            for (int j = 0; j < 4; j++) {
                int k = k0 + (j >> 1) * 8 + (j & 1);
                float val = 0.f;
                if (k < 100) {
                    if (m < 100)       val = Vw[m * DD + k];
                    else if (m == 100) val = sWq[k];
                }
                f[h][j] = val;
            }
        }
        uint32_t r0 = pack_bf16(f[0][0], f[0][1]);
        uint32_t r1 = pack_bf16(f[1][0], f[1][1]);
        uint32_t r2 = pack_bf16(f[0][2], f[0][3]);
        uint32_t r3 = pack_bf16(f[1][2], f[1][3]);
        *(uint4*)(dst + (size_t)((w * KTB + kt) * 32 + ln) * 4) =
            make_uint4(r0, r1, r2, r3);
    }
}

// ---------------------------------------------------------------------------
// Kernel 2: bf16 mma GEMM (7 warps, W+w~ in regs) -> norms^2 + numerator.
// fp32 tile kept for exact t = att@v.
// ---------------------------------------------------------------------------
#define F_V     0                            // fp32 v tile 100x100
#define F_VH    (F_V + 100 * 100)            // bf16 tile: 104 rows x 68 words
#define F_PART  (F_VH + 104 * VHW)           // 7 * 112
#define F_DOT   (F_PART + 7 * 112)           // 112
#define F_ATT   (F_DOT + 112)                // 128
#define SMEM_FLOATS_TOT (F_ATT + 128)

__global__ __launch_bounds__(256, 3) void attn_kernel(
    const float* __restrict__ v,
    const float* __restrict__ Vb)
{
    extern __shared__ float smf[];
    float*    sV    = smf + F_V;
    uint32_t* sVh   = (uint32_t*)(smf + F_VH);
    float*    sPart = smf + F_PART;
    float*    sdot  = smf + F_DOT;
    float*    sAtt  = smf + F_ATT;

    int tid  = threadIdx.x;
    int warp = tid >> 5;
    int lane = tid & 31;
    int g    = lane >> 2;
    int tg   = lane & 3;

    int blk   = blockIdx.x;                  // 2048 blocks
    int b     = blk >> 6;
    int pair0 = (blk & 63) * PAIRS_PER_BLK;

    float cb = g_cb[b];

    // A fragments (bf16) once per block
    uint32_t aW[KTB][4];
    float bias0 = 0.f, bias1 = 0.f, mval0 = 0.f, mval1 = 0.f;
    if (warp < 7) {
        const uint4* src = (const uint4*)(g_Af + (size_t)b * AFB_PER_B)
                         + (size_t)warp * KTB * 32;
        #pragma unroll
        for (int kt = 0; kt < KTB; kt++) {
            uint4 u = src[kt * 32 + lane];
            aW[kt][0] = u.x; aW[kt][1] = u.y; aW[kt][2] = u.z; aW[kt][3] = u.w;
        }
        int m0 = warp * 16 + g, m1 = m0 + 8;
        if (m0 < 100) { bias0 = Vb[m0]; mval0 = 1.f; }
        if (m1 < 100) { bias1 = Vb[m1]; mval1 = 1.f; }
    }

    // one-time zero of bf16 k-pad (words 50..55 = k 100..111) for all 104 rows
    for (int i = tid; i < 104 * 6; i += 256) {
        int r = i / 6, wd = 50 + i % 6;
        sVh[r * VHW + wd] = 0u;
    }

    for (int p = 0; p < PAIRS_PER_BLK; p++) {
        __syncthreads();

        int pp = b * 128 + pair0 + p;
        size_t vbase = (size_t)pp * 10000;
        for (int c = tid; c < 2500; c += 256) {
            int r = c / 25, dq = (c - r * 25) * 4;
            float4 val = *(const float4*)(v + vbase + r * DD + dq);
            *(float4*)(sV + r * 100 + dq) = val;
            uint32_t lo = pack_bf16(val.x, val.y);
            uint32_t hi = pack_bf16(val.z, val.w);
            *(uint2*)(sVh + r * VHW + dq / 2) = make_uint2(lo, hi);
        }
        __syncthreads();

        // ---- GEMM: warps 0..6, bf16 m16n8k16 ----
        if (warp < 7) {
            #pragma unroll 1
            for (int nt = 0; nt < NT; nt++) {
                const uint32_t* br = sVh + (nt * 8 + g) * VHW + tg;
                float c[4] = {0.f, 0.f, 0.f, 0.f};
                #pragma unroll
                for (int kt = 0; kt < KTB; kt++) {
                    uint32_t b0 = br[kt * 8];
                    uint32_t b1 = br[kt * 8 + 4];
                    mma_bf16(c, aW[kt], b0, b1);
                }
                // squares per column (D rows = e features)
                float k0 = c[0] + bias0, k1 = c[1] + bias0;
                float k2 = c[2] + bias1, k3 = c[3] + bias1;
                float s0 = mval0 * k0 * k0 + mval1 * k2 * k2;   // col nt*8+2tg
                float s1 = mval0 * k1 * k1 + mval1 * k3 * k3;   // col +1
                #pragma unroll
                for (int o = 4; o <= 16; o <<= 1) {
                    s0 += __shfl_xor_sync(0xffffffffu, s0, o);
                    s1 += __shfl_xor_sync(0xffffffffu, s1, o);
                }
                if (g == 0) {
                    sPart[warp * 112 + nt * 8 + 2 * tg]     = s0;
                    sPart[warp * 112 + nt * 8 + 2 * tg + 1] = s1;
                }
                if (warp == 6 && g == 4) {     // A row 100 = numerator
                    sdot[nt * 8 + 2 * tg]     = c[0] + cb;
                    sdot[nt * 8 + 2 * tg + 1] = c[1] + cb;
                }
            }
        }
        __syncthreads();

        // ---- softmax per s (warps 0,1) ----
        if (warp < 2) {
            int s = warp;
            int rb = s * 50;
            float x0, x1;
            {
                int r = rb + lane;
                float nrm = 0.f;
                #pragma unroll
                for (int w = 0; w < 7; w++) nrm += sPart[w * 112 + r];
                float l2 = sqrtf(nrm);
                if (l2 == 0.0f) l2 = 1e-6f;
                float sc = sdot[r] / l2;
                sc = (sc == 0.0f) ? -10000.0f : sc;
                x0 = (sc > 0.0f) ? sc : 0.01f * sc;
            }
            x1 = -INFINITY;
            if (lane < NN - 32) {
                int r = rb + lane + 32;
                float nrm = 0.f;
                #pragma unroll
                for (int w = 0; w < 7; w++) nrm += sPart[w * 112 + r];
                float l2 = sqrtf(nrm);
                if (l2 == 0.0f) l2 = 1e-6f;
                float sc = sdot[r] / l2;
                sc = (sc == 0.0f) ? -10000.0f : sc;
                x1 = (sc > 0.0f) ? sc : 0.01f * sc;
            }
            float m = fmaxf(x0, x1);
            #pragma unroll
            for (int o = 16; o; o >>= 1) m = fmaxf(m, __shfl_xor_sync(0xffffffffu, m, o));
            float e0 = expf(x0 - m);
            float e1 = (lane < NN - 32) ? expf(x1 - m) : 0.0f;
            float sm = e0 + e1;
            #pragma unroll
            for (int o = 16; o; o >>= 1) sm += __shfl_xor_sync(0xffffffffu, sm, o);
            float inv = 1.0f / sm;
            float a0 = e0 * inv;
            if (a0 == (1.0f / 50.0f)) a0 = 0.0f;
            float a1 = 0.0f;
            if (lane < NN - 32) {
                a1 = e1 * inv;
                if (a1 == (1.0f / 50.0f)) a1 = 0.0f;
            }
            sAtt[rb + lane] = a0;
            if (lane < NN - 32) sAtt[rb + lane + 32] = a1;
            float sg = a0 + a1;
            #pragma unroll
            for (int o = 16; o; o >>= 1) sg += __shfl_xor_sync(0xffffffffu, sg, o);
            if (lane == 0) g_sig[pp * 2 + s] = sg;
        }
        __syncthreads();

        // ---- t[s][e] = sum_n att[s][n] * v[s*50+n][e]  (exact fp32) ----
        int s = tid >> 7;
        int e = tid & 127;
        if (e < 100) {
            float acc = 0.f;
            const float* ab = sAtt + s * 50;
            const float* kb = sV + (s * 50) * 100 + e;
            #pragma unroll 5
            for (int n = 0; n < NN; n++) acc += ab[n] * kb[n * 100];
            g_T[(size_t)(pp * 2 + s) * DD + e] = acc;
        }
    }
}

// ---------------------------------------------------------------------------
// Kernel 3: out[r][e] = sum_d T[r][d] * W[e][d] + sig[r] * Vb[e]
// 256 threads, 8 rows/block split into two 4-row groups.
// ---------------------------------------------------------------------------
#define OP_ROWS 8
#define WS 101
__global__ __launch_bounds__(256) void out_proj(
    const float* __restrict__ Vw,
    const float* __restrict__ Vb,
    float* __restrict__ out)
{
    __shared__ float sW[DD * WS];          // sW[d*101+e] = Vw[e*100+d]
    __shared__ float sT[OP_ROWS * DD];
    __shared__ float sS[OP_ROWS];

    int tid = threadIdx.x;
    int r0  = blockIdx.x * OP_ROWS;

    for (int i = tid; i < DD * DD; i += 256) {
        int e = i / DD, d = i - e * DD;     // coalesced LDG, conflict-free STS
        sW[d * WS + e] = Vw[i];
    }
    {
        const float4* tsrc = (const float4*)(g_T + (size_t)r0 * DD);
        float4* tdst = (float4*)sT;
        for (int i = tid; i < OP_ROWS * DD / 4; i += 256) tdst[i] = tsrc[i];
        if (tid < OP_ROWS) sS[tid] = g_sig[r0 + tid];
    }
    __syncthreads();

    int grp = tid >> 7;          // 0 or 1 -> rows grp*4 .. grp*4+3
    int e   = tid & 127;
    if (e < DD) {
        float be = Vb[e];
        float acc[4];
        #pragma unroll
        for (int j = 0; j < 4; j++) acc[j] = sS[grp * 4 + j] * be;
        #pragma unroll 4
        for (int d = 0; d < DD; d++) {
            float w = sW[d * WS + e];
            #pragma unroll
            for (int j = 0; j < 4; j++)
                acc[j] += sT[(grp * 4 + j) * DD + d] * w;   // broadcast LDS
        }
        #pragma unroll
        for (int j = 0; j < 4; j++)
            out[(size_t)(r0 + grp * 4 + j) * DD + e] = acc[j];
    }
}

// ---------------------------------------------------------------------------
extern "C" void kernel_launch(void* const* d_in, const int* in_sizes, int n_in,
                              void* d_out, int out_size)
{
    // metadata order: input_ent, q, k, v, Q_w, Q_b, V_w, V_b
    const float* q  = (const float*)d_in[1];
    const float* v  = (const float*)d_in[3];
    const float* Qw = (const float*)d_in[4];
    const float* Qb = (const float*)d_in[5];
    const float* Vw = (const float*)d_in[6];
    const float* Vb = (const float*)d_in[7];
    float* out = (float*)d_out;

    qproj_a<<<BB * DD, 128>>>(q, Qw, Qb);
    qproj_b<<<BB, 128>>>(Vw, Vb);

    size_t smem_bytes = SMEM_FLOATS_TOT * sizeof(float);
    cudaFuncSetAttribute(attn_kernel, cudaFuncAttributeMaxDynamicSharedMemorySize,
                         (int)smem_bytes);
    attn_kernel<<<BB * SS / 2 / PAIRS_PER_BLK, 256, smem_bytes>>>(v, Vb);

    out_proj<<<BB * SS / OP_ROWS, 256>>>(Vw, Vb, out);
}